// round 12
// baseline (speedup 1.0000x reference)
#include <cuda_runtime.h>
#include <cuda_bf16.h>
#include <cstdint>

#define N_WORDS 30000
#define EMB_DIM 784
#define MAT_DIM 28
#define BATCH   1024
#define SEQ     64

// 4 warps per block, one block per sequence, each warp owns a 16-token chunk.
// __launch_bounds__(128, 7): 148*7 = 1036 >= 1024 blocks -> exactly one wave.
#define WARPS_PER_BLOCK 4
#define CHUNK 16
#define THREADS (WARPS_PER_BLOCK * 32)
#define MIN_BLOCKS_PER_SM 7

// Padded matrix layout in smem: 28 rows x 32 floats (128 B row stride).
// Cols 28..31 are zero and stay zero. One matrix = 3584 B.
#define PROW 32
#define MAT_F (MAT_DIM * PROW)   // 896 floats

// ---------------------------------------------------------------------------
// f32x2 packed-FMA helpers
// ---------------------------------------------------------------------------
__device__ __forceinline__ unsigned long long pack2(float x, float y) {
    unsigned long long r;
    asm("mov.b64 %0, {%1, %2};" : "=l"(r) : "f"(x), "f"(y));
    return r;
}
__device__ __forceinline__ void unpack2(unsigned long long d, float& x, float& y) {
    asm("mov.b64 {%0, %1}, %2;" : "=f"(x), "=f"(y) : "l"(d));
}
__device__ __forceinline__ void fma2(unsigned long long& d,
                                     unsigned long long a,
                                     unsigned long long b) {
    asm("fma.rn.f32x2 %0, %1, %2, %0;" : "+l"(d) : "l"(a), "l"(b));
}
__device__ __forceinline__ unsigned long long mul2(unsigned long long a,
                                                   unsigned long long b) {
    unsigned long long d;
    asm("mul.rn.f32x2 %0, %1, %2;" : "=l"(d) : "l"(a), "l"(b));
    return d;
}

// cp.async 16B global -> shared
__device__ __forceinline__ void cp16(void* s, const void* g) {
    unsigned saddr = (unsigned)__cvta_generic_to_shared(s);
    asm volatile("cp.async.cg.shared.global [%0], [%1], 16;\n"
                 :: "r"(saddr), "l"(g) : "memory");
}
__device__ __forceinline__ void cp_commit() {
    asm volatile("cp.async.commit_group;\n" ::: "memory");
}
__device__ __forceinline__ void cp_wait0() {
    asm volatile("cp.async.wait_group 0;\n" ::: "memory");
}

// Warp-cooperative prefetch of one 28x28 fp32 matrix into the PADDED layout.
// Global: 196 contiguous 16B chunks (row-major, 112B rows). Smem: chunk c
// (row c/7, piece c%7) lands at row*128B + piece*16B. Padding col untouched.
__device__ __forceinline__ void prefetch_mat(float* dst, const float* src, int lane) {
#pragma unroll
    for (int i = 0; i < 7; ++i) {
        int c = lane + i * 32;
        if (c < 196) {
            int row = c / 7, piece = c - row * 7;
            cp16(dst + row * PROW + piece * 4, src + c * 4);
        }
    }
    cp_commit();
}

// ---------------------------------------------------------------------------
// Tiled matmul: warp = 4x8 lane grid; lane (a,b) (a=lane>>3, b=lane&7) owns a
// 7x4 tile: rows 7a..7a+6, cols 4b..4b+3 (cols 28..31 are zero padding).
// Per k-step: ONE LDS.128 (8 distinct chunks of M row k across b-groups),
// 7 shfl for the A column, 14 FMA2. 28 LDS.128/matmul vs 196 before.
// ---------------------------------------------------------------------------
__device__ __forceinline__ void matmul28(float cur[7][4], const float* sM, int lane) {
    const int bcol = (lane & 7) * 4;              // this lane's first col
    unsigned long long acc[7][2];

#pragma unroll
    for (int k = 0; k < MAT_DIM; ++k) {
        const ulonglong2 bb =
            *reinterpret_cast<const ulonglong2*>(sM + k * PROW + bcol);
        const int src = (lane & ~7) | (k >> 2);   // lane holding col k of cur
#pragma unroll
        for (int i = 0; i < 7; ++i) {
            float av = __shfl_sync(0xffffffffu, cur[i][k & 3], src);
            unsigned long long a2 = pack2(av, av);
            if (k == 0) {
                acc[i][0] = mul2(a2, bb.x);
                acc[i][1] = mul2(a2, bb.y);
            } else {
                fma2(acc[i][0], a2, bb.x);
                fma2(acc[i][1], a2, bb.y);
            }
        }
    }
#pragma unroll
    for (int i = 0; i < 7; ++i) {
        unpack2(acc[i][0], cur[i][0], cur[i][1]);
        unpack2(acc[i][1], cur[i][2], cur[i][3]);
    }
}

// Store this lane's tile into a padded smem matrix (keeps padding zero:
// b=7 lanes write their all-zero cols 28..31).
__device__ __forceinline__ void store_tile(float* dst, const float cur[7][4], int lane) {
    const int a = lane >> 3, bcol = (lane & 7) * 4;
#pragma unroll
    for (int i = 0; i < 7; ++i)
        *reinterpret_cast<float4*>(dst + (7 * a + i) * PROW + bcol) =
            make_float4(cur[i][0], cur[i][1], cur[i][2], cur[i][3]);
}

// Load this lane's tile from a padded smem matrix.
__device__ __forceinline__ void load_tile(float cur[7][4], const float* src, int lane) {
    const int a = lane >> 3, bcol = (lane & 7) * 4;
#pragma unroll
    for (int i = 0; i < 7; ++i) {
        float4 v = *reinterpret_cast<const float4*>(src + (7 * a + i) * PROW + bcol);
        cur[i][0] = v.x; cur[i][1] = v.y; cur[i][2] = v.z; cur[i][3] = v.w;
    }
}

__global__ void __launch_bounds__(THREADS, MIN_BLOCKS_PER_SM)
w2m_kernel(const int* __restrict__ sent,
           const float* __restrict__ table,
           float* __restrict__ out) {
    // Double-buffered padded right operand per warp; reused as combine scratch.
    // 4 * 2 * 3584 B = 28 KB.
    __shared__ __align__(16) float mbuf[WARPS_PER_BLOCK][2][MAT_F];

    const int seq  = blockIdx.x;
    const int w    = threadIdx.x >> 5;
    const int lane = threadIdx.x & 31;

    // Zero the padding column (cols 28..31) of this warp's two buffers once.
    // Prefetch never touches it; store_tile rewrites zeros -> stays zero.
    if (lane < MAT_DIM) {
        *reinterpret_cast<float4*>(&mbuf[w][0][lane * PROW + MAT_DIM]) =
            make_float4(0.f, 0.f, 0.f, 0.f);
        *reinterpret_cast<float4*>(&mbuf[w][1][lane * PROW + MAT_DIM]) =
            make_float4(0.f, 0.f, 0.f, 0.f);
    }
    __syncwarp();

    // Lane t (<16) holds token index t of this warp's chunk.
    int sidx = 0;
    if (lane < CHUNK) sidx = sent[(size_t)seq * SEQ + w * CHUNK + lane];

    float cur[7][4];

    // Prefetch token 0.
    {
        int idx0 = __shfl_sync(0xffffffffu, sidx, 0);
        prefetch_mat(mbuf[w][0], table + (size_t)idx0 * EMB_DIM, lane);
    }

#pragma unroll 1
    for (int t = 0; t < CHUNK; ++t) {
        cp_wait0();           // token t landed
        __syncwarp();
        if (t < CHUNK - 1) {  // stream token t+1 behind the matmul below
            int idx = __shfl_sync(0xffffffffu, sidx, t + 1);
            prefetch_mat(mbuf[w][(t + 1) & 1], table + (size_t)idx * EMB_DIM, lane);
        }
        if (t == 0) {
            load_tile(cur, mbuf[w][0], lane);
        } else {
            matmul28(cur, mbuf[w][t & 1], lane);
        }
    }

    // ---- Combine (reuse mbuf as padded scratch) ----
    if (w == 1 || w == 3) store_tile(mbuf[w][0], cur, lane);
    __syncthreads();

    if (w == 0 || w == 2) matmul28(cur, mbuf[w + 1][0], lane);   // P0@P1, P2@P3
    if (w == 2) store_tile(mbuf[2][0], cur, lane);
    __syncthreads();

    if (w == 0) {                                                // final product
        matmul28(cur, mbuf[2][0], lane);
        const int a = lane >> 3, b = lane & 7;
        if (b < 7) {   // cols 28..31 are padding
            float* obase = out + (size_t)seq * EMB_DIM;
#pragma unroll
            for (int i = 0; i < 7; ++i)
                *reinterpret_cast<float4*>(obase + (7 * a + i) * MAT_DIM + 4 * b) =
                    make_float4(cur[i][0], cur[i][1], cur[i][2], cur[i][3]);
        }
    }
}

extern "C" void kernel_launch(void* const* d_in, const int* in_sizes, int n_in,
                              void* d_out, int out_size) {
    const int* sent;
    const float* table;
    if (in_sizes[0] == BATCH * SEQ) {
        sent  = (const int*)d_in[0];
        table = (const float*)d_in[1];
    } else {
        sent  = (const int*)d_in[1];
        table = (const float*)d_in[0];
    }
    float* out = (float*)d_out;
    (void)n_in; (void)out_size;

    w2m_kernel<<<BATCH, THREADS>>>(sent, table, out);
}

// round 16
// speedup vs baseline: 1.0559x; 1.0559x over previous
#include <cuda_runtime.h>
#include <cuda_bf16.h>
#include <cstdint>

#define N_WORDS 30000
#define EMB_DIM 784
#define MAT_DIM 28
#define BATCH   1024
#define SEQ     64
#define MAT_BYTES (EMB_DIM * 4)   // 3136

// 4 warps/block, one block per sequence, each warp owns a 16-token chunk.
// __launch_bounds__(128, 7): 148*7 = 1036 >= 1024 -> exactly one wave.
#define WARPS_PER_BLOCK 4
#define CHUNK 16
#define THREADS (WARPS_PER_BLOCK * 32)
#define MIN_BLOCKS_PER_SM 7

// ---------------------------------------------------------------------------
// f32x2 packed-FMA helpers
// ---------------------------------------------------------------------------
__device__ __forceinline__ unsigned long long pack2(float x, float y) {
    unsigned long long r;
    asm("mov.b64 %0, {%1, %2};" : "=l"(r) : "f"(x), "f"(y));
    return r;
}
__device__ __forceinline__ void unpack2(unsigned long long d, float& x, float& y) {
    asm("mov.b64 {%0, %1}, %2;" : "=f"(x), "=f"(y) : "l"(d));
}
__device__ __forceinline__ void fma2(unsigned long long& d,
                                     unsigned long long a,
                                     unsigned long long b) {
    asm("fma.rn.f32x2 %0, %1, %2, %0;" : "+l"(d) : "l"(a), "l"(b));
}
__device__ __forceinline__ unsigned long long mul2(unsigned long long a,
                                                   unsigned long long b) {
    unsigned long long d;
    asm("mul.rn.f32x2 %0, %1, %2;" : "=l"(d) : "l"(a), "l"(b));
    return d;
}

// ---------------------------------------------------------------------------
// Bulk-copy prefetch: ONE cp.async.bulk per matrix (3136 B) instead of 196
// LDGSTS — removes per-16B smem write/issue contention from the L1 pipe.
// ---------------------------------------------------------------------------
__device__ __forceinline__ void mbar_init(void* bar, unsigned count) {
    unsigned a = (unsigned)__cvta_generic_to_shared(bar);
    asm volatile("mbarrier.init.shared.b64 [%0], %1;" :: "r"(a), "r"(count) : "memory");
}
__device__ __forceinline__ void fence_proxy_async_cta() {
    asm volatile("fence.proxy.async.shared::cta;" ::: "memory");
}
// expect_tx + bulk G2S, issued by one lane.
__device__ __forceinline__ void bulk_load(void* smem_dst, const void* gsrc, void* bar) {
    unsigned d = (unsigned)__cvta_generic_to_shared(smem_dst);
    unsigned b = (unsigned)__cvta_generic_to_shared(bar);
    asm volatile("mbarrier.arrive.expect_tx.shared.b64 _, [%0], %1;"
                 :: "r"(b), "r"((unsigned)MAT_BYTES) : "memory");
    asm volatile("cp.async.bulk.shared::cluster.global.mbarrier::complete_tx::bytes "
                 "[%0], [%1], %2, [%3];"
                 :: "r"(d), "l"(gsrc), "r"((unsigned)MAT_BYTES), "r"(b) : "memory");
}
__device__ __forceinline__ void mbar_wait(void* bar, unsigned parity) {
    unsigned b = (unsigned)__cvta_generic_to_shared(bar);
    asm volatile(
        "{\n\t"
        ".reg .pred P;\n\t"
        "W_%=:\n\t"
        "mbarrier.try_wait.parity.acquire.cta.shared::cta.b64 P, [%0], %1, 0x989680;\n\t"
        "@P bra D_%=;\n\t"
        "bra.uni W_%=;\n\t"
        "D_%=:\n\t"
        "}"
        :: "r"(b), "r"(parity) : "memory");
}

// ---------------------------------------------------------------------------
// cur(row r, registers of lane r) = cur @ M, M (28x28 row-major) in shared.
// All lanes read identical addresses -> LDS.128 broadcast (conflict-free).
// 14 mul2 + 378 fma2 + 196 LDS.128 per call.
// ---------------------------------------------------------------------------
__device__ __forceinline__ void matmul28(float cur[MAT_DIM], const float* sM) {
    unsigned long long acc[14];
    {   // k = 0: init accumulators with multiply
        unsigned long long a2 = pack2(cur[0], cur[0]);
        const ulonglong2* row = reinterpret_cast<const ulonglong2*>(sM);
#pragma unroll
        for (int j = 0; j < 7; ++j) {
            ulonglong2 b = row[j];
            acc[2 * j]     = mul2(a2, b.x);
            acc[2 * j + 1] = mul2(a2, b.y);
        }
    }
#pragma unroll
    for (int k = 1; k < MAT_DIM; ++k) {
        unsigned long long a2 = pack2(cur[k], cur[k]);
        const ulonglong2* row = reinterpret_cast<const ulonglong2*>(sM + k * MAT_DIM);
#pragma unroll
        for (int j = 0; j < 7; ++j) {
            ulonglong2 b = row[j];                 // LDS.128 broadcast
            fma2(acc[2 * j],     a2, b.x);
            fma2(acc[2 * j + 1], a2, b.y);
        }
    }
#pragma unroll
    for (int j = 0; j < 14; ++j) unpack2(acc[j], cur[2 * j], cur[2 * j + 1]);
}

__device__ __forceinline__ void store_row_shared(float* dst, const float cur[MAT_DIM]) {
    float4* o = reinterpret_cast<float4*>(dst);
#pragma unroll
    for (int j = 0; j < 7; ++j)
        o[j] = make_float4(cur[4 * j], cur[4 * j + 1], cur[4 * j + 2], cur[4 * j + 3]);
}

__global__ void __launch_bounds__(THREADS, MIN_BLOCKS_PER_SM)
w2m_kernel(const int* __restrict__ sent,
           const float* __restrict__ table,
           float* __restrict__ out) {
    // Double-buffered right operand per warp; reused as combine scratch.
    __shared__ __align__(16) float mbuf[WARPS_PER_BLOCK][2][EMB_DIM];
    __shared__ __align__(8)  unsigned long long mbar[WARPS_PER_BLOCK][2];

    const int seq  = blockIdx.x;
    const int w    = threadIdx.x >> 5;
    const int lane = threadIdx.x & 31;
    const bool active = (lane < MAT_DIM);
    const int r = lane;

    // Init this warp's two mbarriers (arrive count 1 = the expect_tx arrival).
    if (lane == 0) {
        mbar_init(&mbar[w][0], 1);
        mbar_init(&mbar[w][1], 1);
        fence_proxy_async_cta();
    }
    __syncwarp();

    // Lane t (<16) holds token index t of this warp's chunk.
    int sidx = 0;
    if (lane < CHUNK) sidx = sent[(size_t)seq * SEQ + w * CHUNK + lane];

    float cur[MAT_DIM];

    // Prefetch token 0 into buffer 0.
    {
        int idx0 = __shfl_sync(0xffffffffu, sidx, 0);
        if (lane == 0)
            bulk_load(mbuf[w][0], table + (size_t)idx0 * EMB_DIM, &mbar[w][0]);
    }

    // t = 0: issue prefetch(1), wait buf0, cur = M_0.
    {
        int idx = __shfl_sync(0xffffffffu, sidx, 1);
        if (lane == 0)
            bulk_load(mbuf[w][1], table + (size_t)idx * EMB_DIM, &mbar[w][1]);
        mbar_wait(&mbar[w][0], 0);
        if (active) {
            const float4* rowp = reinterpret_cast<const float4*>(&mbuf[w][0][r * MAT_DIM]);
#pragma unroll
            for (int j = 0; j < 7; ++j) {
                float4 v = rowp[j];
                cur[4 * j] = v.x; cur[4 * j + 1] = v.y;
                cur[4 * j + 2] = v.z; cur[4 * j + 3] = v.w;
            }
        }
    }

#pragma unroll 1
    for (int t = 1; t < CHUNK; ++t) {
        // Re-arm + prefetch t+1 into buf[(t+1)&1] (its consumer, matmul t-1,
        // is complete in warp program order; its barrier was waited at t-1).
        if (t < CHUNK - 1) {
            int idx = __shfl_sync(0xffffffffu, sidx, t + 1);
            if (lane == 0)
                bulk_load(mbuf[w][(t + 1) & 1], table + (size_t)idx * EMB_DIM,
                          &mbar[w][(t + 1) & 1]);
        }
        // Wait token t: buffer t&1, parity = (t>>1)&1 (n-th reuse of buffer).
        mbar_wait(&mbar[w][t & 1], (t >> 1) & 1);
        if (active) matmul28(cur, mbuf[w][t & 1]);
    }

    // ---- Combine (all TMA complete; reuse mbuf as scratch) ----
    if (active && (w == 1 || w == 3)) store_row_shared(&mbuf[w][0][r * MAT_DIM], cur);
    __syncthreads();

    if (active && (w == 0 || w == 2)) matmul28(cur, mbuf[w + 1][0]);   // P0@P1, P2@P3
    if (active && w == 2) store_row_shared(&mbuf[2][0][r * MAT_DIM], cur);
    __syncthreads();

    if (active && w == 0) {                                            // final
        matmul28(cur, mbuf[2][0]);
        float4* o = reinterpret_cast<float4*>(out + (size_t)seq * EMB_DIM + r * MAT_DIM);
#pragma unroll
        for (int j = 0; j < 7; ++j)
            o[j] = make_float4(cur[4 * j], cur[4 * j + 1], cur[4 * j + 2], cur[4 * j + 3]);
    }
}

extern "C" void kernel_launch(void* const* d_in, const int* in_sizes, int n_in,
                              void* d_out, int out_size) {
    const int* sent;
    const float* table;
    if (in_sizes[0] == BATCH * SEQ) {
        sent  = (const int*)d_in[0];
        table = (const float*)d_in[1];
    } else {
        sent  = (const int*)d_in[1];
        table = (const float*)d_in[0];
    }
    float* out = (float*)d_out;
    (void)n_in; (void)out_size;

    w2m_kernel<<<BATCH, THREADS>>>(sent, table, out);
}